// round 8
// baseline (speedup 1.0000x reference)
#include <cuda_runtime.h>
#include <stdint.h>

// MXFP (E2M1-like, group=32) quantize-dequantize, bit-exact vs the JAX reference.
// Round 8: persistent single-wave grid-stride kernel. All prior rounds pinned
// at ~6.1 TB/s mixed r/w HBM ceiling with ~7 CTA waves; this eliminates the
// ~6 wave transitions (T_wave_trans ~2360 cyc each) that drain the LSU queues
// and leave DRAM idle between waves. Body = proven R2 structure: 4 coalesced
// slabs (MLP=4 front-batched LDG.128), width-8 3-stage butterfly, magic-add
// RNE, streaming (.cs) loads and stores.

__device__ __forceinline__ float mxfp_q1(float x, float inv_scale, float scale) {
    float xd = x * inv_scale;                       // exact (power-of-two scale)
    uint32_t bb = __float_as_uint(xd);
    uint32_t eb = bb & 0x7F800000u;                 // exponent field
    // mans*2 = |xd| * 2^(1-e);  m2 in [2,4) for normal xd
    float m2 = fabsf(xd) * __uint_as_float(0x7F800000u - eb);
    // RNE to integer via magic constant (matches rintf in this range)
    float r = (m2 + 12582912.0f) - 12582912.0f;
    // x_rnd = r * 2^(e-1)
    float ra = r * __uint_as_float(eb - 0x00800000u);
    ra = fminf(fmaxf(ra, 0.5f), 6.0f);              // clamp [min_repr, max_repr]
    if (fabsf(xd) <= 0.25f) ra = 0.0f;              // lim_zero flush (handles 0/denorm paths)
    uint32_t rb = (__float_as_uint(ra) & 0x7FFFFFFFu) | (bb & 0x80000000u);
    return __uint_as_float(rb) * scale;             // exact (power-of-two scale)
}

__device__ __forceinline__ float maxabs4(float4 v) {
    return fmaxf(fmaxf(fabsf(v.x), fabsf(v.y)), fmaxf(fabsf(v.z), fabsf(v.w)));
}

__device__ __forceinline__ float4 q4(float4 v, float inv_scale, float scale) {
    float4 o;
    o.x = mxfp_q1(v.x, inv_scale, scale);
    o.y = mxfp_q1(v.y, inv_scale, scale);
    o.z = mxfp_q1(v.z, inv_scale, scale);
    o.w = mxfp_q1(v.w, inv_scale, scale);
    return o;
}

__global__ __launch_bounds__(256) void mxfp_kernel(const float4* __restrict__ in,
                                                   float4* __restrict__ out,
                                                   int nq) {
    int stride = gridDim.x * blockDim.x;

    for (int i = blockIdx.x * blockDim.x + threadIdx.x; i < nq; i += stride) {
        // ---- front-batched: 4 independent, fully-coalesced LDG.128 ----
        float4 v[4];
#pragma unroll
        for (int k = 0; k < 4; k++)
            v[k] = __ldcs(in + i + k * nq);

        // ---- local max|.| per chunk ----
        float m[4];
#pragma unroll
        for (int k = 0; k < 4; k++)
            m[k] = maxabs4(v[k]);

        // ---- 4 independent width-8 butterfly reductions, stages interleaved ----
#pragma unroll
        for (int k = 0; k < 4; k++) m[k] = fmaxf(m[k], __shfl_xor_sync(0xFFFFFFFFu, m[k], 1));
#pragma unroll
        for (int k = 0; k < 4; k++) m[k] = fmaxf(m[k], __shfl_xor_sync(0xFFFFFFFFu, m[k], 2));
#pragma unroll
        for (int k = 0; k < 4; k++) m[k] = fmaxf(m[k], __shfl_xor_sync(0xFFFFFFFFu, m[k], 4));

#pragma unroll
        for (int k = 0; k < 4; k++) {
            float mk = (m[k] == 0.0f) ? 1.0f : m[k];
            int e   = (int)(__float_as_uint(mk) >> 23) - 127;  // floor(log2) for normal mk
            int pot = e - 2;
            if (pot < -127) pot = -127;

            float inv_scale = __uint_as_float((uint32_t)(127 - pot) << 23);   // 2^-pot
            float scale = (pot >= -126)
                        ? __uint_as_float((uint32_t)(pot + 127) << 23)        // normal 2^pot
                        : __uint_as_float(0x00400000u);                       // denormal 2^-127

            __stcs(out + i + k * nq, q4(v[k], inv_scale, scale));
        }
    }
}

extern "C" void kernel_launch(void* const* d_in, const int* in_sizes, int n_in,
                              void* d_out, int out_size) {
    const float4* x = (const float4*)d_in[0];
    float4* y = (float4*)d_out;
    int n4 = in_sizes[0] / 4;          // 8,388,608 float4
    int nq = n4 / 4;                   // 2,097,152 float4 per slab
    // Single persistent wave: 152 SMs x 6 CTAs (regs ~40 @ 256 thr -> occ 6).
    int blocks = 152 * 6;              // 912
    int threads = 256;
    mxfp_kernel<<<blocks, threads>>>(x, y, nq);
}

// round 9
// speedup vs baseline: 1.1492x; 1.1492x over previous
#include <cuda_runtime.h>
#include <stdint.h>

// MXFP (E2M1-like, group=32) quantize-dequantize, bit-exact vs the JAX reference.
// Round 9: R2 grid structure (best so far: 4 coalesced slabs, MLP=4, width-8
// butterfly, 256thr x 8192 blocks, .cs streaming both ways) + Veltkamp-split
// rounding: RNE to 2 significant bits via c = fma(xd,2^22,xd); h = c-(c-xd).
// This replaces the exponent-bit-trick sequence (7 mostly-ALU-pipe ops) with
// 3 FMA-pipe ops, halving ALU-pipe pressure and shortening the per-element
// dependency chain. Tie-to-even matches jnp.round (banker's rounding).

__device__ __forceinline__ float mxfp_q1(float x, float inv_scale, float scale) {
    float xd = x * inv_scale;                        // exact (power-of-two scale)
    // Veltkamp: round xd to 2 significant bits, RNE. |xd| < 8 so no overflow.
    float c = fmaf(xd, 4194304.0f, xd);              // xd*(2^22+1), single rounding
    float h = c - (c - xd);                          // RNE(xd -> 2 sig bits)
    // clamp magnitude to [min_repr, max_repr] = [0.5, 6]
    float a = fminf(fmaxf(fabsf(h), 0.5f), 6.0f);
    // lim_zero flush (also covers xd==0 / denormal xd)
    if (fabsf(xd) <= 0.25f) a = 0.0f;
    // reapply sign of xd
    float y = copysignf(a, xd);
    return y * scale;                                // exact (power-of-two scale)
}

__device__ __forceinline__ float maxabs4(float4 v) {
    return fmaxf(fmaxf(fabsf(v.x), fabsf(v.y)), fmaxf(fabsf(v.z), fabsf(v.w)));
}

__device__ __forceinline__ float4 q4(float4 v, float inv_scale, float scale) {
    float4 o;
    o.x = mxfp_q1(v.x, inv_scale, scale);
    o.y = mxfp_q1(v.y, inv_scale, scale);
    o.z = mxfp_q1(v.z, inv_scale, scale);
    o.w = mxfp_q1(v.w, inv_scale, scale);
    return o;
}

__global__ __launch_bounds__(256) void mxfp_kernel(const float4* __restrict__ in,
                                                   float4* __restrict__ out,
                                                   int nq) {
    int i = blockIdx.x * blockDim.x + threadIdx.x;
    if (i >= nq) return;

    // ---- front-batched: 4 independent, fully-coalesced LDG.128 ----
    float4 v[4];
#pragma unroll
    for (int k = 0; k < 4; k++)
        v[k] = __ldcs(in + i + k * nq);

    // ---- local max|.| per chunk ----
    float m[4];
#pragma unroll
    for (int k = 0; k < 4; k++)
        m[k] = maxabs4(v[k]);

    // ---- 4 independent width-8 butterfly reductions, stages interleaved ----
#pragma unroll
    for (int k = 0; k < 4; k++) m[k] = fmaxf(m[k], __shfl_xor_sync(0xFFFFFFFFu, m[k], 1));
#pragma unroll
    for (int k = 0; k < 4; k++) m[k] = fmaxf(m[k], __shfl_xor_sync(0xFFFFFFFFu, m[k], 2));
#pragma unroll
    for (int k = 0; k < 4; k++) m[k] = fmaxf(m[k], __shfl_xor_sync(0xFFFFFFFFu, m[k], 4));

#pragma unroll
    for (int k = 0; k < 4; k++) {
        float mk = (m[k] == 0.0f) ? 1.0f : m[k];
        int e   = (int)(__float_as_uint(mk) >> 23) - 127;  // floor(log2) for normal mk
        int pot = e - 2;
        if (pot < -127) pot = -127;

        float inv_scale = __uint_as_float((uint32_t)(127 - pot) << 23);   // 2^-pot
        float scale = (pot >= -126)
                    ? __uint_as_float((uint32_t)(pot + 127) << 23)        // normal 2^pot
                    : __uint_as_float(0x00400000u);                       // denormal 2^-127

        __stcs(out + i + k * nq, q4(v[k], inv_scale, scale));
    }
}

extern "C" void kernel_launch(void* const* d_in, const int* in_sizes, int n_in,
                              void* d_out, int out_size) {
    const float4* x = (const float4*)d_in[0];
    float4* y = (float4*)d_out;
    int n4 = in_sizes[0] / 4;          // 8,388,608 float4
    int nq = n4 / 4;                   // 2,097,152 per slab
    int threads = 256;
    int blocks = (nq + threads - 1) / threads;   // 8192
    mxfp_kernel<<<blocks, threads>>>(x, y, nq);
}